// round 2
// baseline (speedup 1.0000x reference)
#include <cuda_runtime.h>
#include <cuda_fp16.h>
#include <cstdint>

// ============================================================================
// MultiHeadGraphAttentionLayer — reduced form.
// softmax rows sum to 1, so out = hp = h @ Wcat : [16384,256] x [256,256].
// sm_103 BASE target only (no tcgen05/TMEM — ptxas compiles compute_103):
// classic warp-tiled GEMM with ldmatrix + mma.sync.m16n8k16 (fp16 in, fp32 acc).
// ============================================================================

static constexpr int M_TOTAL = 16384;
static constexpr int N_OUT   = 256;
static constexpr int K_DIM   = 256;

static constexpr int CTA_M   = 128;
static constexpr int CTA_N   = 128;
static constexpr int THREADS = 256;

// padded smem row: 256 + 8 halves -> 528B row stride (16B-aligned, rotates
// bank phase by one 16B chunk per row => conflict-free ldmatrix)
static constexpr int SMEM_LD = K_DIM + 8;  // 264 halves
static constexpr int SMEM_HALVES = CTA_M * SMEM_LD;          // per tile
static constexpr int SMEM_BYTES  = 2 * SMEM_HALVES * 2;      // A + B = 135168

__device__ __forceinline__ uint32_t smem_u32(const void* p) {
    uint32_t a;
    asm("{ .reg .u64 t; cvta.to.shared.u64 t, %1; cvt.u32.u64 %0, t; }"
        : "=r"(a) : "l"(p));
    return a;
}

__device__ __forceinline__ void ldm_x4(uint32_t* r, uint32_t addr) {
    asm volatile("ldmatrix.sync.aligned.m8n8.x4.shared.b16 {%0,%1,%2,%3}, [%4];"
                 : "=r"(r[0]), "=r"(r[1]), "=r"(r[2]), "=r"(r[3])
                 : "r"(addr));
}

__device__ __forceinline__ void mma16816(float* c, const uint32_t* a,
                                         const uint32_t* b) {
    asm volatile(
        "mma.sync.aligned.m16n8k16.row.col.f32.f16.f16.f32 "
        "{%0,%1,%2,%3}, {%4,%5,%6,%7}, {%8,%9}, {%0,%1,%2,%3};"
        : "+f"(c[0]), "+f"(c[1]), "+f"(c[2]), "+f"(c[3])
        : "r"(a[0]), "r"(a[1]), "r"(a[2]), "r"(a[3]), "r"(b[0]), "r"(b[1]));
}

__global__ __launch_bounds__(THREADS, 1)
void gat_gemm_kernel(const float* __restrict__ hin,
                     const float* __restrict__ Win,
                     float* __restrict__ out) {
    extern __shared__ __half smem[];
    __half* As = smem;                 // [128][264]  A = h tile (row-major M x K)
    __half* Bs = smem + SMEM_HALVES;   // [128][264]  B = Wcat^T tile (N x K rows)

    const int tid  = threadIdx.x;
    const int wid  = tid >> 5;
    const int lane = tid & 31;

    const int bm   = blockIdx.x >> 1;        // 0..127
    const int bn   = (blockIdx.x & 1) * CTA_N;  // 0 or 128
    const long arow0 = (long)bm * CTA_M;

    // ---- Stage A: h rows [arow0, arow0+128), fp32 -> fp16 ----
    {
        const float4* h4 = reinterpret_cast<const float4*>(hin + arow0 * K_DIM);
        #pragma unroll 4
        for (int idx = tid; idx < CTA_M * (K_DIM / 4); idx += THREADS) {
            int m  = idx >> 6;       // 64 float4 per row
            int fq = idx & 63;
            float4 v = h4[m * 64 + fq];
            __half2 p0 = __floats2half2_rn(v.x, v.y);
            __half2 p1 = __floats2half2_rn(v.z, v.w);
            uint2 u;
            u.x = *reinterpret_cast<uint32_t*>(&p0);
            u.y = *reinterpret_cast<uint32_t*>(&p1);
            *reinterpret_cast<uint2*>(&As[m * SMEM_LD + fq * 4]) = u;
        }
    }

    // ---- Stage B: Bt[c][f] = W[hh, f, d], c = hh*64+d, local c in [0,128) ----
    // This CTA covers global cols [bn, bn+128) -> heads hh0, hh0+1.
    {
        const float4* W4 = reinterpret_cast<const float4*>(Win);
        const int hh0 = bn >> 6;
        #pragma unroll 4
        for (int idx = tid; idx < 2 * 256 * 16; idx += THREADS) {  // 8192 float4
            int hh = hh0 + (idx >> 12);
            int f  = (idx >> 4) & 255;
            int dq = idx & 15;
            float4 v = W4[hh * 4096 + f * 16 + dq];
            int c = (hh << 6) + dq * 4 - bn;   // local 0..127
            const float* vf = reinterpret_cast<const float*>(&v);
            #pragma unroll
            for (int j = 0; j < 4; j++)
                Bs[(c + j) * SMEM_LD + f] = __float2half_rn(vf[j]);
        }
    }
    __syncthreads();

    // ---- Main loop: warp tile 32(m) x 64(n), 16 k-steps of k16 ----
    const int wm = wid & 3;   // 0..3  (m offset = wm*32)
    const int wn = wid >> 2;  // 0..1  (n offset = wn*64)

    float acc[2][8][4];
    #pragma unroll
    for (int mt = 0; mt < 2; mt++)
        #pragma unroll
        for (int nt = 0; nt < 8; nt++)
            #pragma unroll
            for (int q = 0; q < 4; q++) acc[mt][nt][q] = 0.f;

    // ldmatrix lane addressing
    const int aRow = wm * 32 + (lane & 7) + ((lane >> 3) & 1) * 8;   // + mt*16
    const int aCol = ((lane >> 4) & 1) * 8;                          // + ks*16
    const int bRow = wn * 64 + ((lane >> 4) << 3) + (lane & 7);      // + nt2*16
    const int bCol = ((lane >> 3) & 1) * 8;                          // + ks*16

    const uint32_t aAddr0 = smem_u32(&As[aRow * SMEM_LD + aCol]);
    const uint32_t bAddr0 = smem_u32(&Bs[bRow * SMEM_LD + bCol]);

    #pragma unroll
    for (int ks = 0; ks < 16; ks++) {
        uint32_t a[2][4];
        #pragma unroll
        for (int mt = 0; mt < 2; mt++)
            ldm_x4(a[mt], aAddr0 + (uint32_t)((mt * 16 * SMEM_LD + ks * 16) * 2));
        uint32_t b[4][4];
        #pragma unroll
        for (int nt2 = 0; nt2 < 4; nt2++)
            ldm_x4(b[nt2], bAddr0 + (uint32_t)((nt2 * 16 * SMEM_LD + ks * 16) * 2));
        #pragma unroll
        for (int mt = 0; mt < 2; mt++)
            #pragma unroll
            for (int nt = 0; nt < 8; nt++)
                mma16816(acc[mt][nt], a[mt], &b[nt >> 1][(nt & 1) * 2]);
    }

    // ---- Epilogue: direct fp32 stores ----
    const int g  = lane >> 2;
    const int tg = lane & 3;
    #pragma unroll
    for (int mt = 0; mt < 2; mt++) {
        #pragma unroll
        for (int nt = 0; nt < 8; nt++) {
            long row = arow0 + wm * 32 + mt * 16 + g;
            int  col = bn + wn * 64 + nt * 8 + tg * 2;
            float2 v0 = make_float2(acc[mt][nt][0], acc[mt][nt][1]);
            float2 v1 = make_float2(acc[mt][nt][2], acc[mt][nt][3]);
            *reinterpret_cast<float2*>(out + row * N_OUT + col)       = v0;
            *reinterpret_cast<float2*>(out + (row + 8) * N_OUT + col) = v1;
        }
    }
}

extern "C" void kernel_launch(void* const* d_in, const int* in_sizes, int n_in,
                              void* d_out, int out_size) {
    const float* h = (const float*)d_in[0];
    const float* W = (const float*)d_in[1];
    // metadata order: h (4194304 f32), W (65536 f32). Guard against swap.
    if (n_in >= 2 && in_sizes[0] < in_sizes[1]) {
        const float* t = h; h = W; W = t;
    }
    cudaFuncSetAttribute(gat_gemm_kernel,
                         cudaFuncAttributeMaxDynamicSharedMemorySize, SMEM_BYTES);
    const int grid = (M_TOTAL / CTA_M) * (N_OUT / CTA_N);  // 256
    gat_gemm_kernel<<<grid, THREADS, SMEM_BYTES>>>(h, W, (float*)d_out);
}

// round 3
// speedup vs baseline: 1.3237x; 1.3237x over previous
#include <cuda_runtime.h>
#include <cuda_fp16.h>
#include <cstdint>

// ============================================================================
// MultiHeadGraphAttentionLayer — reduced form.
// softmax rows sum to 1, so out = hp = h @ Wcat : [16384,256] x [256,256].
// sm_103 base ISA (compute_103 PTX — no tcgen05).
// A (h) streamed global->fragment regs with prefetch; only B (Wcat^T) in SMEM.
// ============================================================================

static constexpr int M_TOTAL = 16384;
static constexpr int N_OUT   = 256;
static constexpr int K_DIM   = 256;

static constexpr int CTA_M   = 128;
static constexpr int CTA_N   = 128;
static constexpr int THREADS = 256;

// padded smem row: 256 + 8 halves (16B pad rotates bank phase per row)
static constexpr int SMEM_LD     = K_DIM + 8;               // 264 halves
static constexpr int SMEM_BYTES  = CTA_N * SMEM_LD * 2;     // 67584 (B only)

__device__ __forceinline__ uint32_t smem_u32(const void* p) {
    uint32_t a;
    asm("{ .reg .u64 t; cvta.to.shared.u64 t, %1; cvt.u32.u64 %0, t; }"
        : "=r"(a) : "l"(p));
    return a;
}

__device__ __forceinline__ void ldm_x4(uint32_t* r, uint32_t addr) {
    asm volatile("ldmatrix.sync.aligned.m8n8.x4.shared.b16 {%0,%1,%2,%3}, [%4];"
                 : "=r"(r[0]), "=r"(r[1]), "=r"(r[2]), "=r"(r[3])
                 : "r"(addr));
}

__device__ __forceinline__ void mma16816(float* c, const uint32_t* a,
                                         const uint32_t* b) {
    asm volatile(
        "mma.sync.aligned.m16n8k16.row.col.f32.f16.f16.f32 "
        "{%0,%1,%2,%3}, {%4,%5,%6,%7}, {%8,%9}, {%0,%1,%2,%3};"
        : "+f"(c[0]), "+f"(c[1]), "+f"(c[2]), "+f"(c[3])
        : "r"(a[0]), "r"(a[1]), "r"(a[2]), "r"(a[3]), "r"(b[0]), "r"(b[1]));
}

__device__ __forceinline__ uint32_t pack_h2(float x, float y) {
    __half2 h = __floats2half2_rn(x, y);
    return *reinterpret_cast<uint32_t*>(&h);
}

__global__ __launch_bounds__(THREADS, 2)
void gat_gemm_kernel(const float* __restrict__ hin,
                     const float* __restrict__ Win,
                     float* __restrict__ out) {
    extern __shared__ __half Bs[];     // [128][264]  B = Wcat^T (n-rows, k-cols)

    const int tid  = threadIdx.x;
    const int wid  = tid >> 5;
    const int lane = tid & 31;

    const int bm   = blockIdx.x >> 1;           // 0..127
    const int bn   = (blockIdx.x & 1) * CTA_N;  // 0 or 128
    const long arow0 = (long)bm * CTA_M;

    // ---- Stage B once: Bt[c][f] = W[hh, f, d], c = hh*64+d, local c in [0,128) ----
    {
        const float4* W4 = reinterpret_cast<const float4*>(Win);
        const int hh0 = bn >> 6;
        #pragma unroll 4
        for (int idx = tid; idx < 2 * 256 * 16; idx += THREADS) {  // 8192 float4
            int hh = hh0 + (idx >> 12);
            int f  = (idx >> 4) & 255;
            int dq = idx & 15;
            float4 v = W4[hh * 4096 + f * 16 + dq];
            int c = (hh << 6) + dq * 4 - bn;   // local 0..127
            const float* vf = reinterpret_cast<const float*>(&v);
            #pragma unroll
            for (int j = 0; j < 4; j++)
                Bs[(c + j) * SMEM_LD + f] = __float2half_rn(vf[j]);
        }
    }
    __syncthreads();

    // ---- Warp tiling: 8 warps = 4(m) x 2(n); warp tile 32(m) x 64(n) ----
    const int wm = wid & 3;
    const int wn = wid >> 2;

    float acc[2][8][4];
    #pragma unroll
    for (int mt = 0; mt < 2; mt++)
        #pragma unroll
        for (int nt = 0; nt < 8; nt++)
            #pragma unroll
            for (int q = 0; q < 4; q++) acc[mt][nt][q] = 0.f;

    // B ldmatrix lane addressing (same as verified round-2 kernel)
    const int bRow = wn * 64 + ((lane >> 4) << 3) + (lane & 7);
    const int bCol = ((lane >> 3) & 1) * 8;
    const uint32_t bAddr0 = smem_u32(&Bs[bRow * SMEM_LD + bCol]);

    // A fragment direct-from-global addressing.
    // m16n8k16 A layout: lane r = lane>>2, c0 = (lane&3)*2
    //   a0=(r, c0..c0+1)  a1=(r+8, ...)  a2=(r, c0+8..9)  a3=(r+8, c0+8..9)
    const float* aBase = hin + (arow0 + wm * 32 + (lane >> 2)) * K_DIM
                             + (lane & 3) * 2;

    // prefetch buffers: [mt*4 + j] for j = a0..a3
    float2 cur[8], nxt[8];

    #define LOAD_A(dst, ks) do {                                               \
        _Pragma("unroll")                                                      \
        for (int mt = 0; mt < 2; mt++) {                                       \
            const float* p = aBase + (mt * 16) * K_DIM + (ks) * 16;            \
            (dst)[mt*4+0] = *reinterpret_cast<const float2*>(p);               \
            (dst)[mt*4+1] = *reinterpret_cast<const float2*>(p + 8 * K_DIM);   \
            (dst)[mt*4+2] = *reinterpret_cast<const float2*>(p + 8);           \
            (dst)[mt*4+3] = *reinterpret_cast<const float2*>(p + 8 * K_DIM + 8);\
        }                                                                      \
    } while (0)

    LOAD_A(cur, 0);

    #pragma unroll
    for (int ks = 0; ks < 16; ks++) {
        if (ks < 15) LOAD_A(nxt, ks + 1);

        // convert fp32 pairs -> fp16 fragments
        uint32_t a[2][4];
        #pragma unroll
        for (int mt = 0; mt < 2; mt++)
            #pragma unroll
            for (int j = 0; j < 4; j++)
                a[mt][j] = pack_h2(cur[mt*4+j].x, cur[mt*4+j].y);

        // B fragments from smem
        uint32_t b[4][4];
        #pragma unroll
        for (int nt2 = 0; nt2 < 4; nt2++)
            ldm_x4(b[nt2], bAddr0 + (uint32_t)((nt2 * 16 * SMEM_LD + ks * 16) * 2));

        #pragma unroll
        for (int mt = 0; mt < 2; mt++)
            #pragma unroll
            for (int nt = 0; nt < 8; nt++)
                mma16816(acc[mt][nt], a[mt], &b[nt >> 1][(nt & 1) * 2]);

        #pragma unroll
        for (int j = 0; j < 8; j++) cur[j] = nxt[j];
    }
    #undef LOAD_A

    // ---- Epilogue: direct fp32 stores ----
    const int g  = lane >> 2;
    const int tg = lane & 3;
    #pragma unroll
    for (int mt = 0; mt < 2; mt++) {
        #pragma unroll
        for (int nt = 0; nt < 8; nt++) {
            long row = arow0 + wm * 32 + mt * 16 + g;
            int  col = bn + wn * 64 + nt * 8 + tg * 2;
            float2 v0 = make_float2(acc[mt][nt][0], acc[mt][nt][1]);
            float2 v1 = make_float2(acc[mt][nt][2], acc[mt][nt][3]);
            *reinterpret_cast<float2*>(out + row * N_OUT + col)       = v0;
            *reinterpret_cast<float2*>(out + (row + 8) * N_OUT + col) = v1;
        }
    }
}

extern "C" void kernel_launch(void* const* d_in, const int* in_sizes, int n_in,
                              void* d_out, int out_size) {
    const float* h = (const float*)d_in[0];
    const float* W = (const float*)d_in[1];
    // metadata order: h (4194304 f32), W (65536 f32). Guard against swap.
    if (n_in >= 2 && in_sizes[0] < in_sizes[1]) {
        const float* t = h; h = W; W = t;
    }
    cudaFuncSetAttribute(gat_gemm_kernel,
                         cudaFuncAttributeMaxDynamicSharedMemorySize, SMEM_BYTES);
    const int grid = (M_TOTAL / CTA_M) * (N_OUT / CTA_N);  // 256
    gat_gemm_kernel<<<grid, THREADS, SMEM_BYTES>>>(h, W, (float*)d_out);
}

// round 4
// speedup vs baseline: 1.5044x; 1.1365x over previous
#include <cuda_runtime.h>
#include <cuda_fp16.h>
#include <cstdint>

// ============================================================================
// MultiHeadGraphAttentionLayer — reduced form.
// softmax rows sum to 1, so out = hp = h @ Wcat : [16384,256] x [256,256].
// Two kernels: (1) h fp32 -> fp16 scratch, (2) cp.async double-buffered
// ldmatrix + mma.sync.m16n8k16 GEMM. sm_103 base ISA only.
// ============================================================================

static constexpr int M_TOTAL = 16384;
static constexpr int N_OUT   = 256;
static constexpr int K_DIM   = 256;

static constexpr int CTA_M   = 128;
static constexpr int CTA_N   = 128;
static constexpr int THREADS = 256;

static constexpr int KSLAB   = 64;                 // k-slice per pipeline stage
static constexpr int NSLICE  = K_DIM / KSLAB;      // 4

// B: full tile, padded rows (528B stride -> 16B phase rotation, conflict-free)
static constexpr int B_LD    = K_DIM + 8;          // 264 halves
static constexpr int B_HALVES = CTA_N * B_LD;      // 33792
// A: двойной buffer of 128 x 64 slabs, padded (144B stride)
static constexpr int A_LD    = KSLAB + 8;          // 72 halves
static constexpr int A_HALVES = CTA_M * A_LD;      // 9216 per stage
static constexpr int SMEM_HALVES = B_HALVES + 2 * A_HALVES;
static constexpr int SMEM_BYTES  = SMEM_HALVES * 2;   // 104448

// fp16 copy of h (8 MB) — static device scratch (no allocation)
__device__ __align__(16) __half g_hhalf[(size_t)M_TOTAL * K_DIM];

__device__ __forceinline__ uint32_t smem_u32(const void* p) {
    uint32_t a;
    asm("{ .reg .u64 t; cvta.to.shared.u64 t, %1; cvt.u32.u64 %0, t; }"
        : "=r"(a) : "l"(p));
    return a;
}

__device__ __forceinline__ void ldm_x4(uint32_t* r, uint32_t addr) {
    asm volatile("ldmatrix.sync.aligned.m8n8.x4.shared.b16 {%0,%1,%2,%3}, [%4];"
                 : "=r"(r[0]), "=r"(r[1]), "=r"(r[2]), "=r"(r[3])
                 : "r"(addr));
}

__device__ __forceinline__ void mma16816(float* c, const uint32_t* a,
                                         const uint32_t* b) {
    asm volatile(
        "mma.sync.aligned.m16n8k16.row.col.f32.f16.f16.f32 "
        "{%0,%1,%2,%3}, {%4,%5,%6,%7}, {%8,%9}, {%0,%1,%2,%3};"
        : "+f"(c[0]), "+f"(c[1]), "+f"(c[2]), "+f"(c[3])
        : "r"(a[0]), "r"(a[1]), "r"(a[2]), "r"(a[3]), "r"(b[0]), "r"(b[1]));
}

#define CP_ASYNC_16(smem_addr, gptr)                                           \
    asm volatile("cp.async.cg.shared.global [%0], [%1], 16;"                   \
                 :: "r"(smem_addr), "l"(gptr))
#define CP_ASYNC_COMMIT() asm volatile("cp.async.commit_group;")
#define CP_ASYNC_WAIT(n)  asm volatile("cp.async.wait_group %0;" :: "n"(n))

// ---------------- kernel 1: h fp32 -> fp16 ----------------
__global__ __launch_bounds__(512)
void convert_h_kernel(const float4* __restrict__ in, int n4) {
    int i = blockIdx.x * blockDim.x + threadIdx.x;
    if (i < n4) {
        float4 v = in[i];
        __half2 p0 = __floats2half2_rn(v.x, v.y);
        __half2 p1 = __floats2half2_rn(v.z, v.w);
        uint2 u;
        u.x = *reinterpret_cast<uint32_t*>(&p0);
        u.y = *reinterpret_cast<uint32_t*>(&p1);
        reinterpret_cast<uint2*>(g_hhalf)[i] = u;
    }
}

// ---------------- kernel 2: GEMM ----------------
__global__ __launch_bounds__(THREADS, 2)
void gat_gemm_kernel(const float* __restrict__ Win,
                     float* __restrict__ out) {
    extern __shared__ __half smem[];
    __half* Bs = smem;                        // [128][264]
    __half* As = smem + B_HALVES;             // [2][128][72]

    const int tid  = threadIdx.x;
    const int wid  = tid >> 5;
    const int lane = tid & 31;

    const int bm   = blockIdx.x >> 1;
    const int bn   = (blockIdx.x & 1) * CTA_N;
    const long arow0 = (long)bm * CTA_M;

    const __half* aGlob = g_hhalf + arow0 * K_DIM;

    // issue A slab for slice 0 into stage 0 (overlaps with B staging)
    {
        #pragma unroll
        for (int i = 0; i < 4; i++) {
            int c   = tid + i * THREADS;        // 0..1023
            int row = c >> 3;
            int c8  = c & 7;
            uint32_t dst = smem_u32(&As[row * A_LD + c8 * 8]);
            CP_ASYNC_16(dst, aGlob + row * K_DIM + c8 * 8);
        }
        CP_ASYNC_COMMIT();
    }

    // stage B: Bt[c][f] = W[hh, f, d], c = hh*64+d (verified round-3 code)
    {
        const float4* W4 = reinterpret_cast<const float4*>(Win);
        const int hh0 = bn >> 6;
        #pragma unroll 4
        for (int idx = tid; idx < 2 * 256 * 16; idx += THREADS) {
            int hh = hh0 + (idx >> 12);
            int f  = (idx >> 4) & 255;
            int dq = idx & 15;
            float4 v = W4[hh * 4096 + f * 16 + dq];
            int c = (hh << 6) + dq * 4 - bn;
            const float* vf = reinterpret_cast<const float*>(&v);
            #pragma unroll
            for (int j = 0; j < 4; j++)
                Bs[(c + j) * B_LD + f] = __float2half_rn(vf[j]);
        }
    }

    // warp tiling: 8 warps = 4(m) x 2(n); warp tile 32(m) x 64(n)
    const int wm = wid & 3;
    const int wn = wid >> 2;

    float acc[2][8][4];
    #pragma unroll
    for (int mt = 0; mt < 2; mt++)
        #pragma unroll
        for (int nt = 0; nt < 8; nt++)
            #pragma unroll
            for (int q = 0; q < 4; q++) acc[mt][nt][q] = 0.f;

    // B ldmatrix lane addressing (as verified)
    const int bRow = wn * 64 + ((lane >> 4) << 3) + (lane & 7);
    const int bCol = ((lane >> 3) & 1) * 8;
    const uint32_t bAddr0 = smem_u32(&Bs[bRow * B_LD + bCol]);

    // A ldmatrix lane addressing: row-major 16x16 block, 4x 8x8 matrices
    // lanes 0-15 -> rows 0-15 col 0 ; lanes 16-31 -> rows 0-15 col 8
    const int aLaneOff = (lane & 15) * A_LD + (lane >> 4) * 8;
    const uint32_t asBase = smem_u32(As);

    int buf = 0;
    #pragma unroll
    for (int slice = 0; slice < NSLICE; slice++) {
        // prefetch next slab into other buffer
        if (slice < NSLICE - 1) {
            const __half* src = aGlob + (slice + 1) * KSLAB;
            #pragma unroll
            for (int i = 0; i < 4; i++) {
                int c   = tid + i * THREADS;
                int row = c >> 3;
                int c8  = c & 7;
                uint32_t dst = smem_u32(&As[(buf ^ 1) * A_HALVES + row * A_LD + c8 * 8]);
                CP_ASYNC_16(dst, src + row * K_DIM + c8 * 8);
            }
            CP_ASYNC_COMMIT();
            CP_ASYNC_WAIT(1);
        } else {
            CP_ASYNC_WAIT(0);
        }
        __syncthreads();

        const uint32_t aSlab = asBase + (uint32_t)((buf * A_HALVES + aLaneOff) * 2);
        #pragma unroll
        for (int ks = 0; ks < 4; ks++) {
            uint32_t a[2][4];
            #pragma unroll
            for (int mt = 0; mt < 2; mt++)
                ldm_x4(a[mt], aSlab + (uint32_t)(((wm * 32 + mt * 16) * A_LD + ks * 16) * 2));

            const int kg = slice * 4 + ks;
            uint32_t b[4][4];
            #pragma unroll
            for (int nt2 = 0; nt2 < 4; nt2++)
                ldm_x4(b[nt2], bAddr0 + (uint32_t)((nt2 * 16 * B_LD + kg * 16) * 2));

            #pragma unroll
            for (int mt = 0; mt < 2; mt++)
                #pragma unroll
                for (int nt = 0; nt < 8; nt++)
                    mma16816(acc[mt][nt], a[mt], &b[nt >> 1][(nt & 1) * 2]);
        }
        __syncthreads();   // protect buf before it is refilled next iteration
        buf ^= 1;
    }

    // epilogue: direct fp32 stores
    const int g  = lane >> 2;
    const int tg = lane & 3;
    #pragma unroll
    for (int mt = 0; mt < 2; mt++) {
        #pragma unroll
        for (int nt = 0; nt < 8; nt++) {
            long row = arow0 + wm * 32 + mt * 16 + g;
            int  col = bn + wn * 64 + nt * 8 + tg * 2;
            float2 v0 = make_float2(acc[mt][nt][0], acc[mt][nt][1]);
            float2 v1 = make_float2(acc[mt][nt][2], acc[mt][nt][3]);
            *reinterpret_cast<float2*>(out + row * N_OUT + col)       = v0;
            *reinterpret_cast<float2*>(out + (row + 8) * N_OUT + col) = v1;
        }
    }
}

extern "C" void kernel_launch(void* const* d_in, const int* in_sizes, int n_in,
                              void* d_out, int out_size) {
    const float* h = (const float*)d_in[0];
    const float* W = (const float*)d_in[1];
    if (n_in >= 2 && in_sizes[0] < in_sizes[1]) {
        const float* t = h; h = W; W = t;
    }
    const int n4 = M_TOTAL * K_DIM / 4;  // 1048576
    convert_h_kernel<<<(n4 + 511) / 512, 512>>>(
        reinterpret_cast<const float4*>(h), n4);

    cudaFuncSetAttribute(gat_gemm_kernel,
                         cudaFuncAttributeMaxDynamicSharedMemorySize, SMEM_BYTES);
    const int grid = (M_TOTAL / CTA_M) * (N_OUT / CTA_N);  // 256
    gat_gemm_kernel<<<grid, THREADS, SMEM_BYTES>>>(W, (float*)d_out);
}

// round 5
// speedup vs baseline: 2.2119x; 1.4703x over previous
#include <cuda_runtime.h>
#include <cuda_fp16.h>
#include <cstdint>

// ============================================================================
// MultiHeadGraphAttentionLayer — reduced form.
// softmax rows sum to 1, so out = hp = h @ Wcat : [16384,256] x [256,256].
// Prepass builds fp16 images of A (row-major) and B (swizzled SMEM image);
// GEMM is pure cp.async (triple-buffered A, verbatim B) + ldmatrix + mma.
// sm_103 base ISA only.
// ============================================================================

static constexpr int M_TOTAL = 16384;
static constexpr int N_OUT   = 256;
static constexpr int K_DIM   = 256;

static constexpr int CTA_M   = 128;
static constexpr int CTA_N   = 128;
static constexpr int THREADS = 256;

static constexpr int KSLAB   = 64;
static constexpr int NSLICE  = K_DIM / KSLAB;   // 4

static constexpr int B_IMG_HALVES = CTA_N * K_DIM;          // 32768 (64 KB)
static constexpr int A_SLAB_BYTES = CTA_M * KSLAB * 2;      // 16384
static constexpr int SMEM_BYTES   = B_IMG_HALVES * 2 + 3 * A_SLAB_BYTES; // 114688

// static device scratch (no allocation): fp16 h + two swizzled B images
__device__ __align__(16) __half g_hhalf[(size_t)M_TOTAL * K_DIM];   // 8 MB
__device__ __align__(16) __half g_bt[2 * B_IMG_HALVES];             // 128 KB

__device__ __forceinline__ uint32_t smem_u32(const void* p) {
    uint32_t a;
    asm("{ .reg .u64 t; cvta.to.shared.u64 t, %1; cvt.u32.u64 %0, t; }"
        : "=r"(a) : "l"(p));
    return a;
}

__device__ __forceinline__ void ldm_x4(uint32_t* r, uint32_t addr) {
    asm volatile("ldmatrix.sync.aligned.m8n8.x4.shared.b16 {%0,%1,%2,%3}, [%4];"
                 : "=r"(r[0]), "=r"(r[1]), "=r"(r[2]), "=r"(r[3])
                 : "r"(addr));
}

__device__ __forceinline__ void mma16816(float* c, const uint32_t* a,
                                         const uint32_t* b) {
    asm volatile(
        "mma.sync.aligned.m16n8k16.row.col.f32.f16.f16.f32 "
        "{%0,%1,%2,%3}, {%4,%5,%6,%7}, {%8,%9}, {%0,%1,%2,%3};"
        : "+f"(c[0]), "+f"(c[1]), "+f"(c[2]), "+f"(c[3])
        : "r"(a[0]), "r"(a[1]), "r"(a[2]), "r"(a[3]), "r"(b[0]), "r"(b[1]));
}

#define CP_ASYNC_16(smem_addr, gptr)                                           \
    asm volatile("cp.async.cg.shared.global [%0], [%1], 16;"                   \
                 :: "r"(smem_addr), "l"(gptr))
#define CP_ASYNC_COMMIT() asm volatile("cp.async.commit_group;")
#define CP_ASYNC_WAIT(n)  asm volatile("cp.async.wait_group %0;" :: "n"(n))

// B image byte offset for local row c (0..127), col f (0..255):
// blocked SW128 atoms: atom = (c>>3) + (f>>6)*16, 1024 B each.
__device__ __forceinline__ uint32_t b_img_off(int c, int f) {
    uint32_t off = (uint32_t)(((c >> 3) + (f >> 6) * 16) * 1024
                              + (c & 7) * 128 + (f & 63) * 2);
    return off ^ ((off >> 3) & 0x70);
}

// ---------------- prepass: h fp32->fp16 + B images ----------------
__global__ __launch_bounds__(512)
void prep_kernel(const float4* __restrict__ h4, const float* __restrict__ W) {
    const int n4 = M_TOTAL * K_DIM / 4;   // 1048576
    int t = blockIdx.x * blockDim.x + threadIdx.x;
    if (t < n4) {
        float4 v = h4[t];
        __half2 p0 = __floats2half2_rn(v.x, v.y);
        __half2 p1 = __floats2half2_rn(v.z, v.w);
        uint2 u;
        u.x = *reinterpret_cast<uint32_t*>(&p0);
        u.y = *reinterpret_cast<uint32_t*>(&p1);
        reinterpret_cast<uint2*>(g_hhalf)[t] = u;
    } else {
        int u = t - n4;                  // 0..65535 -> B images
        if (u < 2 * B_IMG_HALVES) {
            int img = u >> 15;           // bn half
            int rem = u & 32767;
            int f   = rem >> 7;          // 0..255
            int c   = rem & 127;         // local col (consecutive -> coalesced d)
            int n   = img * 128 + c;
            int hh  = n >> 6;
            int d   = n & 63;
            float w = W[hh * 16384 + f * 64 + d];
            g_bt[img * B_IMG_HALVES + (b_img_off(c, f) >> 1)] = __float2half_rn(w);
        }
    }
}

// ---------------- GEMM ----------------
__global__ __launch_bounds__(THREADS, 2)
void gat_gemm_kernel(float* __restrict__ out) {
    extern __shared__ __half smem[];
    __half* Bs = smem;                        // 64 KB swizzled image
    __half* As = smem + B_IMG_HALVES;         // 3 x 16 KB slabs

    const int tid  = threadIdx.x;
    const int wid  = tid >> 5;
    const int lane = tid & 31;

    const int bm   = blockIdx.x >> 1;
    const int img  = blockIdx.x & 1;
    const int bn   = img * CTA_N;
    const long arow0 = (long)bm * CTA_M;

    const __half* aGlob = g_hhalf + arow0 * K_DIM;
    const uint32_t BsU = smem_u32(Bs);
    const uint32_t AsU = smem_u32(As);

    // A slab staging helper: 1024 x 16B chunks, SW128 swizzled rows of 128 B
    #define ISSUE_A(slice, buf) do {                                           \
        const __half* _src = aGlob + (slice) * KSLAB;                          \
        _Pragma("unroll")                                                      \
        for (int i = 0; i < 4; i++) {                                          \
            int c   = tid + i * THREADS;                                       \
            int r   = c >> 3;                                                  \
            int c8  = c & 7;                                                   \
            uint32_t dst = AsU + (uint32_t)((buf) * A_SLAB_BYTES + r * 128     \
                                            + ((c8 * 16) ^ ((r & 7) << 4)));  \
            CP_ASYNC_16(dst, _src + r * K_DIM + c8 * 8);                       \
        }                                                                      \
    } while (0)

    // group 0: A slab 0 + B image (verbatim 64 KB copy)
    ISSUE_A(0, 0);
    {
        const __half* bSrc = g_bt + img * B_IMG_HALVES;
        #pragma unroll
        for (int i = 0; i < 16; i++) {
            int c = tid + i * THREADS;             // 0..4095 chunks
            CP_ASYNC_16(BsU + (uint32_t)(c * 16), bSrc + c * 8);
        }
    }
    CP_ASYNC_COMMIT();
    // group 1: A slab 1
    ISSUE_A(1, 1);
    CP_ASYNC_COMMIT();

    // ---- warp tiling: 8 warps = 4(m) x 2(n); warp tile 32(m) x 64(n) ----
    const int wm = wid & 3;
    const int wn = wid >> 2;

    float acc[2][8][4];
    #pragma unroll
    for (int mt = 0; mt < 2; mt++)
        #pragma unroll
        for (int nt = 0; nt < 8; nt++)
            #pragma unroll
            for (int q = 0; q < 4; q++) acc[mt][nt][q] = 0.f;

    // A lane addressing: row r = wm*32 + (lane&15) (+mt*16), k-col (lane>>4)*8
    const int arl   = wm * 32 + (lane & 15);
    const uint32_t aXor = (uint32_t)((arl & 7) << 4);
    const uint32_t aRowB = (uint32_t)(arl * 128);
    const int akl = (lane >> 4) * 8;

    // B lane addressing: n-row rB = wn*64 + ((lane>>4)<<3) + (lane&7) (+nt2*16)
    //                    k-col f0 = ((lane>>3)&1)*8 (+kg*16)
    const int rB    = wn * 64 + ((lane >> 4) << 3) + (lane & 7);
    const uint32_t bXor = (uint32_t)((rB & 7) << 4);
    const int bkl   = ((lane >> 3) & 1) * 8;
    uint32_t bBase[4];
    #pragma unroll
    for (int nt2 = 0; nt2 < 4; nt2++) {
        int r = rB + nt2 * 16;
        bBase[nt2] = BsU + (uint32_t)((r >> 3) * 1024 + (r & 7) * 128);
    }

    #pragma unroll
    for (int s = 0; s < NSLICE; s++) {
        if (s == NSLICE - 1) { CP_ASYNC_WAIT(0); } else { CP_ASYNC_WAIT(1); }
        __syncthreads();
        if (s + 2 < NSLICE) {            // buffer (s+2)%3 == (s-1)%3 is free now
            ISSUE_A(s + 2, (s + 2) % 3);
            CP_ASYNC_COMMIT();
        }

        const uint32_t aStage = AsU + (uint32_t)((s % 3) * A_SLAB_BYTES);
        #pragma unroll
        for (int ks = 0; ks < 4; ks++) {
            const int kg = s * 4 + ks;
            uint32_t a[2][4];
            #pragma unroll
            for (int mt = 0; mt < 2; mt++) {
                uint32_t addr = aStage + aRowB + (uint32_t)(mt * 16 * 128)
                              + (uint32_t)(((akl + ks * 16) * 2) ^ aXor);
                ldm_x4(a[mt], addr);
            }
            uint32_t b[4][4];
            const uint32_t kOff = (uint32_t)((kg >> 2) * 16384)
                                + (uint32_t)((((kg & 3) * 16 + bkl) * 2) ^ bXor);
            #pragma unroll
            for (int nt2 = 0; nt2 < 4; nt2++)
                ldm_x4(b[nt2], bBase[nt2] + kOff);

            #pragma unroll
            for (int mt = 0; mt < 2; mt++)
                #pragma unroll
                for (int nt = 0; nt < 8; nt++)
                    mma16816(acc[mt][nt], a[mt], &b[nt >> 1][(nt & 1) * 2]);
        }
    }
    #undef ISSUE_A

    // ---- epilogue: direct fp32 stores ----
    const int g  = lane >> 2;
    const int tg = lane & 3;
    #pragma unroll
    for (int mt = 0; mt < 2; mt++) {
        #pragma unroll
        for (int nt = 0; nt < 8; nt++) {
            long row = arow0 + wm * 32 + mt * 16 + g;
            int  col = bn + wn * 64 + nt * 8 + tg * 2;
            float2 v0 = make_float2(acc[mt][nt][0], acc[mt][nt][1]);
            float2 v1 = make_float2(acc[mt][nt][2], acc[mt][nt][3]);
            *reinterpret_cast<float2*>(out + row * N_OUT + col)       = v0;
            *reinterpret_cast<float2*>(out + (row + 8) * N_OUT + col) = v1;
        }
    }
}

extern "C" void kernel_launch(void* const* d_in, const int* in_sizes, int n_in,
                              void* d_out, int out_size) {
    const float* h = (const float*)d_in[0];
    const float* W = (const float*)d_in[1];
    if (n_in >= 2 && in_sizes[0] < in_sizes[1]) {
        const float* t = h; h = W; W = t;
    }
    const int n_threads = M_TOTAL * K_DIM / 4 + 2 * B_IMG_HALVES;  // 1114112
    prep_kernel<<<(n_threads + 511) / 512, 512>>>(
        reinterpret_cast<const float4*>(h), W);

    cudaFuncSetAttribute(gat_gemm_kernel,
                         cudaFuncAttributeMaxDynamicSharedMemorySize, SMEM_BYTES);
    const int grid = (M_TOTAL / CTA_M) * (N_OUT / CTA_N);  // 256
    gat_gemm_kernel<<<grid, THREADS, SMEM_BYTES>>>((float*)d_out);
}

// round 6
// speedup vs baseline: 2.2538x; 1.0189x over previous
#include <cuda_runtime.h>
#include <cuda_fp16.h>
#include <cstdint>

// ============================================================================
// MultiHeadGraphAttentionLayer — reduced form.
// softmax rows sum to 1, so out = hp = h @ Wcat : [16384,256] x [256,256].
// Tiny prepass builds swizzled fp16 B images of Wcat^T; GEMM reads fp32 h
// directly (LDG + in-register fp16 convert, double-buffered slabs) and B via
// verbatim cp.async. ldmatrix + mma.sync.m16n8k16. sm_103 base ISA only.
// ============================================================================

static constexpr int M_TOTAL = 16384;
static constexpr int N_OUT   = 256;
static constexpr int K_DIM   = 256;

static constexpr int CTA_M   = 128;
static constexpr int CTA_N   = 128;
static constexpr int THREADS = 256;

static constexpr int KSLAB   = 64;
static constexpr int NSLICE  = K_DIM / KSLAB;   // 4

static constexpr int B_IMG_HALVES = CTA_N * K_DIM;          // 32768 (64 KB)
static constexpr int A_SLAB_BYTES = CTA_M * KSLAB * 2;      // 16384
static constexpr int SMEM_BYTES   = B_IMG_HALVES * 2 + 2 * A_SLAB_BYTES; // 98304

// swizzled fp16 B images (128 KB) — static device scratch (no allocation)
__device__ __align__(16) __half g_bt[2 * B_IMG_HALVES];

__device__ __forceinline__ uint32_t smem_u32(const void* p) {
    uint32_t a;
    asm("{ .reg .u64 t; cvta.to.shared.u64 t, %1; cvt.u32.u64 %0, t; }"
        : "=r"(a) : "l"(p));
    return a;
}

__device__ __forceinline__ void ldm_x4(uint32_t* r, uint32_t addr) {
    asm volatile("ldmatrix.sync.aligned.m8n8.x4.shared.b16 {%0,%1,%2,%3}, [%4];"
                 : "=r"(r[0]), "=r"(r[1]), "=r"(r[2]), "=r"(r[3])
                 : "r"(addr));
}

__device__ __forceinline__ void mma16816(float* c, const uint32_t* a,
                                         const uint32_t* b) {
    asm volatile(
        "mma.sync.aligned.m16n8k16.row.col.f32.f16.f16.f32 "
        "{%0,%1,%2,%3}, {%4,%5,%6,%7}, {%8,%9}, {%0,%1,%2,%3};"
        : "+f"(c[0]), "+f"(c[1]), "+f"(c[2]), "+f"(c[3])
        : "r"(a[0]), "r"(a[1]), "r"(a[2]), "r"(a[3]), "r"(b[0]), "r"(b[1]));
}

__device__ __forceinline__ uint32_t pack_h2(float x, float y) {
    __half2 h = __floats2half2_rn(x, y);
    return *reinterpret_cast<uint32_t*>(&h);
}

#define CP_ASYNC_16(smem_addr, gptr)                                           \
    asm volatile("cp.async.cg.shared.global [%0], [%1], 16;"                   \
                 :: "r"(smem_addr), "l"(gptr))
#define CP_ASYNC_COMMIT() asm volatile("cp.async.commit_group;")
#define CP_ASYNC_WAIT(n)  asm volatile("cp.async.wait_group %0;" :: "n"(n))

// B image byte offset for local row c (0..127), col f (0..255)
__device__ __forceinline__ uint32_t b_img_off(int c, int f) {
    uint32_t off = (uint32_t)(((c >> 3) + (f >> 6) * 16) * 1024
                              + (c & 7) * 128 + (f & 63) * 2);
    return off ^ ((off >> 3) & 0x70);
}

// ---------------- prepass: B images only ----------------
__global__ __launch_bounds__(512)
void prep_b_kernel(const float* __restrict__ W) {
    int u = blockIdx.x * blockDim.x + threadIdx.x;   // 0..65535
    if (u < 2 * B_IMG_HALVES) {
        int img = u >> 15;
        int rem = u & 32767;
        int f   = rem >> 7;          // 0..255
        int c   = rem & 127;         // local col (consecutive -> coalesced d)
        int n   = img * 128 + c;
        int hh  = n >> 6;
        int d   = n & 63;
        float w = W[hh * 16384 + f * 64 + d];
        g_bt[img * B_IMG_HALVES + (b_img_off(c, f) >> 1)] = __float2half_rn(w);
    }
}

// ---------------- GEMM (fused fp32->fp16 A staging) ----------------
__global__ __launch_bounds__(THREADS, 2)
void gat_gemm_kernel(const float* __restrict__ hin,
                     float* __restrict__ out) {
    extern __shared__ __half smem[];
    __half* Bs = smem;                        // 64 KB swizzled image
    __half* As = smem + B_IMG_HALVES;         // 2 x 16 KB slabs

    const int tid  = threadIdx.x;
    const int wid  = tid >> 5;
    const int lane = tid & 31;

    const int bm   = blockIdx.x >> 1;
    const int img  = blockIdx.x & 1;
    const int bn   = img * CTA_N;
    const long arow0 = (long)bm * CTA_M;

    const float4* aG4 = reinterpret_cast<const float4*>(hin + arow0 * K_DIM);
    const uint32_t BsU = smem_u32(Bs);
    const uint32_t AsU = smem_u32(As);

    // staging indices: 8 chunks per thread; chunk c -> row r = c>>4, q = c&15
    // src: aG4[r*64 + slab*16 + q]  dst: As + buf*16384 + r*128 + ((q*8)^((r&7)<<4))
    uint2 pf[8];

    #define LDG_SLAB(s) do {                                                   \
        _Pragma("unroll")                                                      \
        for (int i = 0; i < 8; i++) {                                          \
            int c = tid + i * THREADS;                                         \
            int r = c >> 4, q = c & 15;                                        \
            float4 v = aG4[r * 64 + (s) * 16 + q];                             \
            pf[i].x = pack_h2(v.x, v.y);                                       \
            pf[i].y = pack_h2(v.z, v.w);                                       \
        }                                                                      \
    } while (0)

    #define STS_SLAB(buf) do {                                                 \
        _Pragma("unroll")                                                      \
        for (int i = 0; i < 8; i++) {                                          \
            int c = tid + i * THREADS;                                         \
            int r = c >> 4, q = c & 15;                                        \
            uint32_t off = (uint32_t)((buf) * A_SLAB_BYTES + r * 128           \
                                      + ((q * 8) ^ ((r & 7) << 4)));          \
            *reinterpret_cast<uint2*>(reinterpret_cast<char*>(As) + off) = pf[i]; \
        }                                                                      \
    } while (0)

    // B image verbatim copy (issue first so the fetch overlaps LDG staging)
    {
        const __half* bSrc = g_bt + img * B_IMG_HALVES;
        #pragma unroll
        for (int i = 0; i < 16; i++) {
            int c = tid + i * THREADS;
            CP_ASYNC_16(BsU + (uint32_t)(c * 16), bSrc + c * 8);
        }
        CP_ASYNC_COMMIT();
    }

    // head: slab0 -> buf0, prefetch slab1 into regs
    LDG_SLAB(0);
    STS_SLAB(0);
    LDG_SLAB(1);
    CP_ASYNC_WAIT(0);
    __syncthreads();

    // ---- warp tiling: 8 warps = 4(m) x 2(n); warp tile 32(m) x 64(n) ----
    const int wm = wid & 3;
    const int wn = wid >> 2;

    float acc[2][8][4];
    #pragma unroll
    for (int mt = 0; mt < 2; mt++)
        #pragma unroll
        for (int nt = 0; nt < 8; nt++)
            #pragma unroll
            for (int q = 0; q < 4; q++) acc[mt][nt][q] = 0.f;

    const int arl   = wm * 32 + (lane & 15);
    const uint32_t aXor  = (uint32_t)((arl & 7) << 4);
    const uint32_t aRowB = (uint32_t)(arl * 128);
    const int akl = (lane >> 4) * 8;

    const int rB    = wn * 64 + ((lane >> 4) << 3) + (lane & 7);
    const uint32_t bXor = (uint32_t)((rB & 7) << 4);
    const int bkl   = ((lane >> 3) & 1) * 8;
    uint32_t bBase[4];
    #pragma unroll
    for (int nt2 = 0; nt2 < 4; nt2++) {
        int r = rB + nt2 * 16;
        bBase[nt2] = BsU + (uint32_t)((r >> 3) * 1024 + (r & 7) * 128);
    }

    #pragma unroll
    for (int s = 0; s < NSLICE; s++) {
        if (s > 0) __syncthreads();           // all warps done reading buf (s+1)&1
        if (s < NSLICE - 1) STS_SLAB((s + 1) & 1);
        if (s < NSLICE - 2) LDG_SLAB(s + 2);

        const uint32_t aStage = AsU + (uint32_t)((s & 1) * A_SLAB_BYTES);
        #pragma unroll
        for (int ks = 0; ks < 4; ks++) {
            const int kg = s * 4 + ks;
            uint32_t a[2][4];
            #pragma unroll
            for (int mt = 0; mt < 2; mt++) {
                uint32_t addr = aStage + aRowB + (uint32_t)(mt * 16 * 128)
                              + (uint32_t)(((akl + ks * 16) * 2) ^ aXor);
                ldm_x4(a[mt], addr);
            }
            uint32_t b[4][4];
            const uint32_t kOff = (uint32_t)((kg >> 2) * 16384)
                                + (uint32_t)((((kg & 3) * 16 + bkl) * 2) ^ bXor);
            #pragma unroll
            for (int nt2 = 0; nt2 < 4; nt2++)
                ldm_x4(b[nt2], bBase[nt2] + kOff);

            #pragma unroll
            for (int mt = 0; mt < 2; mt++)
                #pragma unroll
                for (int nt = 0; nt < 8; nt++)
                    mma16816(acc[mt][nt], a[mt], &b[nt >> 1][(nt & 1) * 2]);
        }
    }
    #undef LDG_SLAB
    #undef STS_SLAB

    // ---- epilogue: direct fp32 stores ----
    const int g  = lane >> 2;
    const int tg = lane & 3;
    #pragma unroll
    for (int mt = 0; mt < 2; mt++) {
        #pragma unroll
        for (int nt = 0; nt < 8; nt++) {
            long row = arow0 + wm * 32 + mt * 16 + g;
            int  col = bn + wn * 64 + nt * 8 + tg * 2;
            float2 v0 = make_float2(acc[mt][nt][0], acc[mt][nt][1]);
            float2 v1 = make_float2(acc[mt][nt][2], acc[mt][nt][3]);
            *reinterpret_cast<float2*>(out + row * N_OUT + col)       = v0;
            *reinterpret_cast<float2*>(out + (row + 8) * N_OUT + col) = v1;
        }
    }
}

extern "C" void kernel_launch(void* const* d_in, const int* in_sizes, int n_in,
                              void* d_out, int out_size) {
    const float* h = (const float*)d_in[0];
    const float* W = (const float*)d_in[1];
    if (n_in >= 2 && in_sizes[0] < in_sizes[1]) {
        const float* t = h; h = W; W = t;
    }
    prep_b_kernel<<<(2 * B_IMG_HALVES + 511) / 512, 512>>>(W);

    cudaFuncSetAttribute(gat_gemm_kernel,
                         cudaFuncAttributeMaxDynamicSharedMemorySize, SMEM_BYTES);
    const int grid = (M_TOTAL / CTA_M) * (N_OUT / CTA_N);  // 256
    gat_gemm_kernel<<<grid, THREADS, SMEM_BYTES>>>(h, (float*)d_out);
}